// round 2
// baseline (speedup 1.0000x reference)
#include <cuda_runtime.h>
#include <cstdint>

// CapsuleLayer: v = routing(reshape(x @ W, [B,16,32]))
//   x: [32768, 512] f32, W: [512, 512] f32, out v: [32768, 32] f32
//
// Kernel 1: fp32-accurate GEMM via 3-term TF32 split (Markidis):
//           u = hi(x)hi(W) + hi(x)lo(W) + lo(x)hi(W)  -> __device__ scratch
// Kernel 2: warp-per-row dynamic routing (3 iters) -> out

#define K_DIM 512
#define N_DIM 512
#define NUM_CAPS 16
#define OUT_DIM 32

#define BM 128
#define BN 128
#define BK 8
#define XS_STRIDE (BM + 4)   // 132 floats
#define WS_STRIDE (BN + 4)   // 132 floats
#define MAX_BATCH 32768

// 64 MB scratch for u (__device__ global, no allocation)
__device__ float g_u[(size_t)MAX_BATCH * N_DIM];

__device__ __forceinline__ float f2tf32(float x) {
    uint32_t u;
    asm("cvt.rna.tf32.f32 %0, %1;" : "=r"(u) : "f"(x));
    return __uint_as_float(u);
}

__device__ __forceinline__ void mma_m16n8k8_tf32(float d[4], const uint32_t a[4],
                                                 const uint32_t b[2]) {
    asm volatile(
        "mma.sync.aligned.m16n8k8.row.col.f32.tf32.tf32.f32 "
        "{%0,%1,%2,%3}, {%4,%5,%6,%7}, {%8,%9}, {%0,%1,%2,%3};\n"
        : "+f"(d[0]), "+f"(d[1]), "+f"(d[2]), "+f"(d[3])
        : "r"(a[0]), "r"(a[1]), "r"(a[2]), "r"(a[3]), "r"(b[0]), "r"(b[1]));
}

// ---------------------------------------------------------------------------
// GEMM: C[M,512] = X[M,512] @ W[512,512], fp32-accurate via TF32 split.
// Block tile 128x128, K-chunk 8, 256 threads (8 warps as 4(m) x 2(n)),
// warp tile 32x64 = 2(m16) x 8(n8) fragments. hi/lo staged in smem.
// ---------------------------------------------------------------------------
__global__ void __launch_bounds__(256)
capsule_gemm_kernel(const float* __restrict__ X, const float* __restrict__ W) {
    __shared__ __align__(16) float XsH[2][BK][XS_STRIDE];
    __shared__ __align__(16) float XsL[2][BK][XS_STRIDE];
    __shared__ __align__(16) float WsH[2][BK][WS_STRIDE];
    __shared__ __align__(16) float WsL[2][BK][WS_STRIDE];

    const int tid = threadIdx.x;
    const int n0 = blockIdx.x * BN;   // n fast-varying -> X tile L2 reuse
    const int m0 = blockIdx.y * BM;

    const int warp = tid >> 5;
    const int lane = tid & 31;
    const int wm = warp >> 1;         // 0..3 -> 32 rows
    const int wn = warp & 1;          // 0..1 -> 64 cols
    const int g = lane >> 2;          // 0..7
    const int t = lane & 3;           // 0..3

    // staging indices: X tile 128x8 (1 float4/thread), W tile 8x128 (1 float4/thread)
    const int xr  = tid >> 1;         // 0..127
    const int xk  = (tid & 1) << 2;   // 0 or 4
    const int wk  = tid >> 5;         // 0..7
    const int wn4 = (tid & 31) << 2;  // 0..124

    float acc[2][8][4];
#pragma unroll
    for (int i = 0; i < 2; i++)
#pragma unroll
        for (int j = 0; j < 8; j++)
#pragma unroll
            for (int q = 0; q < 4; q++) acc[i][j][q] = 0.f;

    const float* Xbase = X + (size_t)m0 * K_DIM;
    const float* Wbase = W + n0;

    float4 xv, wv;

    auto ldg_tiles = [&](int kb) {
        xv = *reinterpret_cast<const float4*>(Xbase + (size_t)xr * K_DIM + kb + xk);
        wv = *reinterpret_cast<const float4*>(Wbase + (size_t)(kb + wk) * N_DIM + wn4);
    };

    auto sts_tiles = [&](int buf) {
        float h, l;
        const float xs[4] = {xv.x, xv.y, xv.z, xv.w};
#pragma unroll
        for (int j = 0; j < 4; j++) {
            h = f2tf32(xs[j]);
            l = f2tf32(xs[j] - h);
            XsH[buf][xk + j][xr] = h;
            XsL[buf][xk + j][xr] = l;
        }
        float4 vh, vl;
        h = f2tf32(wv.x); vh.x = h; vl.x = f2tf32(wv.x - h);
        h = f2tf32(wv.y); vh.y = h; vl.y = f2tf32(wv.y - h);
        h = f2tf32(wv.z); vh.z = h; vl.z = f2tf32(wv.z - h);
        h = f2tf32(wv.w); vh.w = h; vl.w = f2tf32(wv.w - h);
        *reinterpret_cast<float4*>(&WsH[buf][wk][wn4]) = vh;
        *reinterpret_cast<float4*>(&WsL[buf][wk][wn4]) = vl;
    };

    auto compute = [&](int buf) {
        uint32_t aH[2][4], aL[2][4];
        uint32_t bH[8][2], bL[8][2];
#pragma unroll
        for (int i = 0; i < 2; i++) {
            const int mr = wm * 32 + i * 16 + g;
            aH[i][0] = __float_as_uint(XsH[buf][t][mr]);
            aH[i][1] = __float_as_uint(XsH[buf][t][mr + 8]);
            aH[i][2] = __float_as_uint(XsH[buf][t + 4][mr]);
            aH[i][3] = __float_as_uint(XsH[buf][t + 4][mr + 8]);
            aL[i][0] = __float_as_uint(XsL[buf][t][mr]);
            aL[i][1] = __float_as_uint(XsL[buf][t][mr + 8]);
            aL[i][2] = __float_as_uint(XsL[buf][t + 4][mr]);
            aL[i][3] = __float_as_uint(XsL[buf][t + 4][mr + 8]);
        }
#pragma unroll
        for (int j = 0; j < 8; j++) {
            const int nc = wn * 64 + j * 8 + g;
            bH[j][0] = __float_as_uint(WsH[buf][t][nc]);
            bH[j][1] = __float_as_uint(WsH[buf][t + 4][nc]);
            bL[j][0] = __float_as_uint(WsL[buf][t][nc]);
            bL[j][1] = __float_as_uint(WsL[buf][t + 4][nc]);
        }
#pragma unroll
        for (int i = 0; i < 2; i++)
#pragma unroll
            for (int j = 0; j < 8; j++) {
                mma_m16n8k8_tf32(acc[i][j], aH[i], bH[j]);  // hi*hi
                mma_m16n8k8_tf32(acc[i][j], aH[i], bL[j]);  // hi*lo
                mma_m16n8k8_tf32(acc[i][j], aL[i], bH[j]);  // lo*hi
            }
    };

    // software pipeline: LDG(next) -> compute(cur) -> STS(next) -> barrier
    ldg_tiles(0);
    sts_tiles(0);
    __syncthreads();

    const int NKT = K_DIM / BK;  // 64
    for (int kt = 0; kt < NKT; kt++) {
        const int buf = kt & 1;
        if (kt + 1 < NKT) ldg_tiles((kt + 1) * BK);
        compute(buf);
        if (kt + 1 < NKT) sts_tiles(buf ^ 1);
        __syncthreads();
    }

    // epilogue -> g_u
#pragma unroll
    for (int i = 0; i < 2; i++) {
#pragma unroll
        for (int j = 0; j < 8; j++) {
            const int row = m0 + wm * 32 + i * 16 + g;
            const int col = n0 + wn * 64 + j * 8 + t * 2;
            *reinterpret_cast<float2*>(&g_u[(size_t)row * N_DIM + col]) =
                make_float2(acc[i][j][0], acc[i][j][1]);
            *reinterpret_cast<float2*>(&g_u[(size_t)(row + 8) * N_DIM + col]) =
                make_float2(acc[i][j][2], acc[i][j][3]);
        }
    }
}

// ---------------------------------------------------------------------------
// Routing: one warp per batch row. lane = output dim d (0..31).
// ---------------------------------------------------------------------------
__global__ void __launch_bounds__(256)
capsule_routing_kernel(float* __restrict__ out, int batch) {
    const int gw = (int)((blockIdx.x * blockDim.x + threadIdx.x) >> 5);
    const int lane = threadIdx.x & 31;
    if (gw >= batch) return;

    const float* urow = g_u + (size_t)gw * N_DIM;
    float u[NUM_CAPS];
#pragma unroll
    for (int c = 0; c < NUM_CAPS; c++) u[c] = urow[c * OUT_DIM + lane];

    float b[NUM_CAPS];
#pragma unroll
    for (int c = 0; c < NUM_CAPS; c++) b[c] = 0.f;

    float v = 0.f;
#pragma unroll
    for (int it = 0; it < 3; it++) {
        // softmax over capsules (replicated per lane)
        float mx = b[0];
#pragma unroll
        for (int c = 1; c < NUM_CAPS; c++) mx = fmaxf(mx, b[c]);
        float e[NUM_CAPS], sum = 0.f;
#pragma unroll
        for (int c = 0; c < NUM_CAPS; c++) {
            e[c] = expf(b[c] - mx);
            sum += e[c];
        }
        const float inv = 1.f / sum;

        // s[lane] = sum_c softmax(b)[c] * u[c][lane]
        float s = 0.f;
#pragma unroll
        for (int c = 0; c < NUM_CAPS; c++) s = fmaf(e[c] * inv, u[c], s);

        // squash: warp allreduce of ||s||^2 over 32 dims
        float norm = s * s;
#pragma unroll
        for (int o = 16; o; o >>= 1) norm += __shfl_xor_sync(0xffffffffu, norm, o);
        const float vscale = (norm / (1.f + norm)) / (sqrtf(norm) + 1e-8f);
        v = vscale * s;

        // b update (skip last iter: unused)
        if (it < 2) {
#pragma unroll
            for (int c = 0; c < NUM_CAPS; c++) {
                float p = u[c] * v;
#pragma unroll
                for (int o = 16; o; o >>= 1) p += __shfl_xor_sync(0xffffffffu, p, o);
                b[c] += p;
            }
        }
    }

    out[(size_t)gw * OUT_DIM + lane] = v;
}

// ---------------------------------------------------------------------------
extern "C" void kernel_launch(void* const* d_in, const int* in_sizes, int n_in,
                              void* d_out, int out_size) {
    const float* X = (const float*)d_in[0];   // [batch, 512]
    const float* W = (const float*)d_in[1];   // [512, 512]
    float* out = (float*)d_out;               // [batch, 32]

    const int batch = in_sizes[0] / K_DIM;    // 32768

    dim3 ggrid(N_DIM / BN, batch / BM);       // (4, 256)
    capsule_gemm_kernel<<<ggrid, 256>>>(X, W);

    const int rthreads = batch * 32;
    capsule_routing_kernel<<<(rthreads + 255) / 256, 256>>>(out, batch);
}